// round 9
// baseline (speedup 1.0000x reference)
#include <cuda_runtime.h>
#include <cstdint>

namespace {

constexpr int NUM_HEADS = 14;
constexpr int BROWS  = 1024;
constexpr int DIN    = 1920;
constexpr int DSLICE = 128;
constexpr int HID    = NUM_HEADS * DSLICE;   // 1792
constexpr int PMAX   = 36928;

constexpr int BM = 128, BK = 32;
constexpr int SST = BK + 4;

// head kernel: 64-col N-tiles (all p % 64 == 0 -> exact tiling, no guards)
__constant__ int c_p[NUM_HEADS] =
    {9280,18496,36928,36928,36928,36928,36928,36928,36928,18496,9280,18496,18496,9280};
__constant__ int c_tile_start64[NUM_HEADS] =
    {0,145,434,1011,1588,2165,2742,3319,3896,4473,4762,4907,5196,5485};
__constant__ int c_cum[NUM_HEADS] =
    {0,9280,27776,64704,101632,138560,175488,212416,249344,286272,304768,314048,332544,351040};

constexpr int TOTAL_NTILES64 = 5630;
constexpr int MTILES = BROWS / BM;           // 8

constexpr int TILE_FLOATS = BM * DSLICE;     // 16384 floats = 64KB (A tile)
constexpr int BTILE64 = 64 * DSLICE;         // 8192 floats = 32KB (B tile)

// head smem: B 32KB + single A buffer 64KB = 96KB  -> 2 CTAs/SM
constexpr size_t HEAD_SMEM_BYTES = (size_t)(BTILE64 + TILE_FLOATS) * sizeof(float);

// hidden activations in A-FRAGMENT-MAJOR 128-row tiles: [head][mtile][16384]
__device__ float g_hfrag[(size_t)NUM_HEADS * MTILES * TILE_FLOATS];

__device__ __forceinline__ uint32_t f2tf32(float f) {
    uint32_t r;
    asm("cvt.rna.tf32.f32 %0, %1;" : "=r"(r) : "f"(f));
    return r;
}

__device__ __forceinline__ void mma_tf32(float* c, const uint32_t* a, const uint32_t* b) {
    asm volatile(
        "mma.sync.aligned.m16n8k8.row.col.f32.tf32.tf32.f32 "
        "{%0,%1,%2,%3}, {%4,%5,%6,%7}, {%8,%9}, {%0,%1,%2,%3};\n"
        : "+f"(c[0]), "+f"(c[1]), "+f"(c[2]), "+f"(c[3])
        : "r"(a[0]), "r"(a[1]), "r"(a[2]), "r"(a[3]),
          "r"(b[0]), "r"(b[1]));
}

__device__ __forceinline__ void cp_async16_s(uint32_t dst_smem, const float* src) {
    asm volatile("cp.async.cg.shared.global [%0], [%1], 16;\n" :: "r"(dst_smem), "l"(src));
}

// A-fragment-major float index within a 128x128 tile (verified R6 layout).
// float4 idx = (kstep*8 + rb)*32 + lane ; elem = er + 2*ec
__device__ __forceinline__ int afrag_idx(int m, int k) {
    int rb = m >> 4, m16 = m & 15, lr = m16 & 7, er = m16 >> 3;
    int kstep = k >> 3, k8 = k & 7, la3 = k8 & 3, ec = k8 >> 2;
    return ((((kstep << 3) + rb) * 32 + (lr << 2) + la3) << 2) + er + (ec << 1);
}

// B-fragment-major float index for a 64(out-col)x128(k) tile, single col-group.
// float4 idx = (kstep*4 + (j>>1))*32 + lane ; elem = (j&1)*2 + (k8>=4)
__device__ __forceinline__ int bfrag_idx64(int row, int k) {
    int j = row >> 3, lr = row & 7;
    int kstep = k >> 3, la3 = k & 3, b1 = ((k & 7) >= 4);
    return ((((kstep << 2) + (j >> 1)) * 32 + (lr << 2) + la3) << 2)
           + ((j & 1) << 1) + b1;
}

// ---------------------------------------------------------------------------
// Kernel A: hidden = relu(x @ W_hidden^T + b_hidden), tf32-rounded, scattered
//   into A-fragment-major tiles g_hfrag[h][mt]. 64-col N-tiles -> 224 CTAs.
// ---------------------------------------------------------------------------
__global__ void __launch_bounds__(256)
hidden_gemm(const float* __restrict__ x,
            const float* __restrict__ Wh,
            const float* __restrict__ bh)
{
    __shared__ float As[BM][SST];
    __shared__ float Bs[64][SST];

    const int mtile = blockIdx.x & 7;
    const int nt64  = blockIdx.x >> 3;        // 0..27
    const int m0 = mtile * BM;
    const int n0 = nt64 * 64;

    const int tid  = threadIdx.x;
    const int lane = tid & 31;
    const int warp = tid >> 5;
    const int wm = warp >> 1;   // 0..3
    const int wn = warp & 1;    // 0..1   (32-col groups)

    float acc[2][4][4];
    #pragma unroll
    for (int t = 0; t < 2; ++t)
        #pragma unroll
        for (int j = 0; j < 4; ++j)
            #pragma unroll
            for (int q = 0; q < 4; ++q) acc[t][j][q] = 0.f;

    for (int k0 = 0; k0 < DIN; k0 += BK) {
        #pragma unroll
        for (int it = 0; it < 4; ++it) {
            int slot = tid + it * 256;
            int r  = slot >> 3;
            int c4 = (slot & 7) * 4;
            float4 va = *reinterpret_cast<const float4*>(
                x + (size_t)(m0 + r) * DIN + k0 + c4);
            As[r][c4 + 0] = __uint_as_float(f2tf32(va.x));
            As[r][c4 + 1] = __uint_as_float(f2tf32(va.y));
            As[r][c4 + 2] = __uint_as_float(f2tf32(va.z));
            As[r][c4 + 3] = __uint_as_float(f2tf32(va.w));
        }
        #pragma unroll
        for (int it = 0; it < 2; ++it) {
            int slot = tid + it * 256;
            int r  = slot >> 3;                 // 0..63
            int c4 = (slot & 7) * 4;
            float4 vb = *reinterpret_cast<const float4*>(
                Wh + (size_t)(n0 + r) * DIN + k0 + c4);
            Bs[r][c4 + 0] = __uint_as_float(f2tf32(vb.x));
            Bs[r][c4 + 1] = __uint_as_float(f2tf32(vb.y));
            Bs[r][c4 + 2] = __uint_as_float(f2tf32(vb.z));
            Bs[r][c4 + 3] = __uint_as_float(f2tf32(vb.w));
        }
        __syncthreads();

        #pragma unroll
        for (int ks = 0; ks < BK; ks += 8) {
            uint32_t a[2][4];
            #pragma unroll
            for (int t = 0; t < 2; ++t) {
                int row = wm * 32 + t * 16 + (lane >> 2);
                int kc  = ks + (lane & 3);
                a[t][0] = __float_as_uint(As[row][kc]);
                a[t][1] = __float_as_uint(As[row + 8][kc]);
                a[t][2] = __float_as_uint(As[row][kc + 4]);
                a[t][3] = __float_as_uint(As[row + 8][kc + 4]);
            }
            #pragma unroll
            for (int j = 0; j < 4; ++j) {
                int col = wn * 32 + j * 8 + (lane >> 2);
                int kc  = ks + (lane & 3);
                uint32_t b[2];
                b[0] = __float_as_uint(Bs[col][kc]);
                b[1] = __float_as_uint(Bs[col][kc + 4]);
                mma_tf32(acc[0][j], a[0], b);
                mma_tf32(acc[1][j], a[1], b);
            }
        }
        __syncthreads();
    }

    // Epilogue: bias + relu + tf32 round -> A-fragment-major scatter.
    const int head = nt64 >> 1;
    const int kh   = (nt64 & 1) * 64;            // k-offset within head slice
    float* Hf = g_hfrag + ((size_t)head * MTILES + mtile) * TILE_FLOATS;
    const int lr2  = lane >> 2;
    const int la32 = lane & 3;
    #pragma unroll
    for (int t = 0; t < 2; ++t) {
        #pragma unroll
        for (int j = 0; j < 4; ++j) {
            int klocal = wn * 32 + j * 8 + 2 * la32;   // 0..63
            float b0 = bh[n0 + klocal], b1 = bh[n0 + klocal + 1];
            int kbase = kh + klocal;                   // 0..127
            int mA = wm * 32 + t * 16 + lr2;
            Hf[afrag_idx(mA,     kbase    )] =
                __uint_as_float(f2tf32(fmaxf(acc[t][j][0] + b0, 0.f)));
            Hf[afrag_idx(mA,     kbase + 1)] =
                __uint_as_float(f2tf32(fmaxf(acc[t][j][1] + b1, 0.f)));
            Hf[afrag_idx(mA + 8, kbase    )] =
                __uint_as_float(f2tf32(fmaxf(acc[t][j][2] + b0, 0.f)));
            Hf[afrag_idx(mA + 8, kbase + 1)] =
                __uint_as_float(f2tf32(fmaxf(acc[t][j][3] + b1, 0.f)));
        }
    }
}

// ---------------------------------------------------------------------------
// Kernel B: 128 threads (4 warps), warp tile 32x64, one CTA per 64-col N-tile.
//   B fragment-major resident (32KB); A single 64KB buffer refilled per M-tile
//   (copy overlaps epilogue; the co-resident CTA covers remaining bubbles).
//   2 CTAs/SM. No bounds guards (exact 64-col tiling).
// ---------------------------------------------------------------------------
__global__ void __launch_bounds__(128, 2)
head_gemm(const float* __restrict__ Wheads,
          const float* __restrict__ bheads,
          float* __restrict__ out)
{
    extern __shared__ float smem[];
    float* sB = smem;                        // 8192 floats
    float* sA = smem + BTILE64;              // 16384 floats

    const int ntg = blockIdx.x;
    int h = 0;
    #pragma unroll
    for (int i = 1; i < NUM_HEADS; ++i) h += (ntg >= c_tile_start64[i]);
    const int ntile = ntg - c_tile_start64[h];
    const int p  = c_p[h];
    const int n0 = ntile * 64;

    const float* Bg    = Wheads + (size_t)h * PMAX * DSLICE;
    const float* bias  = bheads + (size_t)h * PMAX;
    float* Og = out + (size_t)c_cum[h] * BROWS;
    const float* Hf = g_hfrag + (size_t)h * MTILES * TILE_FLOATS;

    const int tid  = threadIdx.x;
    const int lane = tid & 31;
    const int wm   = tid >> 5;     // warp 0..3 -> 32-row group
    const int la3 = lane & 3;
    const int lr  = lane >> 2;

    const uint32_t sA_u = (uint32_t)__cvta_generic_to_shared(sA);

    // prefetch A tile 0 (contiguous 64KB)
    #pragma unroll
    for (int it = 0; it < 32; ++it) {
        int fo = (it * 128 + tid) * 4;
        cp_async16_s(sA_u + fo * 4, Hf + fo);
    }
    asm volatile("cp.async.commit_group;\n");

    // load B tile once -> fragment-major smem (64 rows x 128 k)
    #pragma unroll
    for (int it = 0; it < 16; ++it) {
        int slot = it * 128 + tid;           // 0..2047
        int row = slot >> 5;                 // 0..63
        int k4  = (slot & 31) * 4;
        float4 v = *reinterpret_cast<const float4*>(
            Bg + (size_t)(n0 + row) * DSLICE + k4);
        sB[bfrag_idx64(row, k4    )] = __uint_as_float(f2tf32(v.x));
        sB[bfrag_idx64(row, k4 + 1)] = __uint_as_float(f2tf32(v.y));
        sB[bfrag_idx64(row, k4 + 2)] = __uint_as_float(f2tf32(v.z));
        sB[bfrag_idx64(row, k4 + 3)] = __uint_as_float(f2tf32(v.w));
    }

    // hoist bias (same columns every M-tile)
    float bs0[8], bs1[8];
    #pragma unroll
    for (int j = 0; j < 8; ++j) {
        int col = n0 + j * 8 + 2 * la3;
        bs0[j] = bias[col];
        bs1[j] = bias[col + 1];
    }

    const float4* sB4 = reinterpret_cast<const float4*>(sB);
    const float4* sA4 = reinterpret_cast<const float4*>(sA);

    asm volatile("cp.async.wait_group 0;\n" ::: "memory");
    __syncthreads();

    for (int mt = 0; mt < MTILES; ++mt) {
        float acc[2][8][4];
        #pragma unroll
        for (int t = 0; t < 2; ++t)
            #pragma unroll
            for (int j = 0; j < 8; ++j)
                #pragma unroll
                for (int q = 0; q < 4; ++q) acc[t][j][q] = 0.f;

        // explicit 1-deep register pipeline over 16 ksteps
        float4 a_cur[2], a_nxt[2], b_cur[4], b_nxt[4];
        #pragma unroll
        for (int t = 0; t < 2; ++t)
            a_cur[t] = sA4[(wm * 2 + t) * 32 + lane];
        #pragma unroll
        for (int jp = 0; jp < 4; ++jp)
            b_cur[jp] = sB4[jp * 32 + lane];

        #pragma unroll
        for (int ks = 0; ks < 16; ++ks) {
            if (ks + 1 < 16) {
                #pragma unroll
                for (int t = 0; t < 2; ++t)
                    a_nxt[t] = sA4[((ks + 1) * 8 + wm * 2 + t) * 32 + lane];
                #pragma unroll
                for (int jp = 0; jp < 4; ++jp)
                    b_nxt[jp] = sB4[((ks + 1) * 4 + jp) * 32 + lane];
            }
            const uint32_t* a0 = reinterpret_cast<const uint32_t*>(&a_cur[0]);
            const uint32_t* a1 = reinterpret_cast<const uint32_t*>(&a_cur[1]);
            #pragma unroll
            for (int jp = 0; jp < 4; ++jp) {
                const uint32_t* bp = reinterpret_cast<const uint32_t*>(&b_cur[jp]);
                uint32_t bj0[2] = {bp[0], bp[1]};
                uint32_t bj1[2] = {bp[2], bp[3]};
                mma_tf32(acc[0][jp * 2],     a0, bj0);
                mma_tf32(acc[1][jp * 2],     a1, bj0);
                mma_tf32(acc[0][jp * 2 + 1], a0, bj1);
                mma_tf32(acc[1][jp * 2 + 1], a1, bj1);
            }
            #pragma unroll
            for (int t = 0; t < 2; ++t) a_cur[t] = a_nxt[t];
            #pragma unroll
            for (int jp = 0; jp < 4; ++jp) b_cur[jp] = b_nxt[jp];
        }

        // all warps done reading sA -> refill it for mt+1 (overlaps epilogue)
        __syncthreads();
        if (mt + 1 < MTILES) {
            const float* src = Hf + (size_t)(mt + 1) * TILE_FLOATS;
            #pragma unroll
            for (int it = 0; it < 32; ++it) {
                int fo = (it * 128 + tid) * 4;
                cp_async16_s(sA_u + fo * 4, src + fo);
            }
            asm volatile("cp.async.commit_group;\n");
        }

        // epilogue (overlaps the in-flight A copy)
        const int m0 = mt * BM;
        #pragma unroll
        for (int t = 0; t < 2; ++t) {
            int row = m0 + wm * 32 + t * 16 + lr;
            #pragma unroll
            for (int j = 0; j < 8; ++j) {
                int col = n0 + j * 8 + 2 * la3;
                float2 v0 = make_float2(acc[t][j][0] + bs0[j], acc[t][j][1] + bs1[j]);
                float2 v1 = make_float2(acc[t][j][2] + bs0[j], acc[t][j][3] + bs1[j]);
                *reinterpret_cast<float2*>(&Og[(size_t)row * p + col])       = v0;
                *reinterpret_cast<float2*>(&Og[(size_t)(row + 8) * p + col]) = v1;
            }
        }

        if (mt + 1 < MTILES) {
            asm volatile("cp.async.wait_group 0;\n" ::: "memory");
            __syncthreads();
        }
    }
}

} // anonymous namespace

extern "C" void kernel_launch(void* const* d_in, const int* in_sizes, int n_in,
                              void* d_out, int out_size) {
    (void)in_sizes; (void)n_in; (void)out_size;
    const float* x      = (const float*)d_in[0];
    const float* Wh     = (const float*)d_in[1];
    const float* bh     = (const float*)d_in[2];
    const float* Wheads = (const float*)d_in[3];
    const float* bheads = (const float*)d_in[4];
    float* out = (float*)d_out;

    static bool attr_set = false;
    if (!attr_set) {
        cudaFuncSetAttribute(head_gemm,
                             cudaFuncAttributeMaxDynamicSharedMemorySize,
                             (int)HEAD_SMEM_BYTES);
        attr_set = true;
    }

    hidden_gemm<<<MTILES * (HID / 64), 256>>>(x, Wh, bh);
    head_gemm<<<TOTAL_NTILES64, 128, HEAD_SMEM_BYTES>>>(Wheads, bheads, out);
}